// round 2
// baseline (speedup 1.0000x reference)
#include <cuda_runtime.h>
#include <cstring>
#include <cmath>
#include <complex>

// ---------------------------------------------------------------------------
// Problem constants (fixed by the dataset)
// ---------------------------------------------------------------------------
#define FDIM 25              // (L_MAX+1)^2
#define NF 64                // feature / radial dim
#define NS 375               // total S entries (sum over triples of 2*l3+1)
#define NE_MAX 15625         // upper bound on CG nonzeros
#define NATOM_MAX 4096
#define NPAIR_MAX 131072
#define NP 8                 // pairs per chunk (register tile)

// 65 valid (l1,l2,l3) triples for L_MAX=4 with running S-offset.
// X(l1, l2, l3, soff) ; soff advances by 2*l3+1 each entry, total 375.
#define TRI_LIST(X) \
X(0,0,0,0) X(0,1,1,1) X(0,2,2,4) X(0,3,3,9) X(0,4,4,16) \
X(1,0,1,25) X(1,1,0,28) X(1,1,1,29) X(1,1,2,32) X(1,2,1,37) X(1,2,2,40) X(1,2,3,45) \
X(1,3,2,52) X(1,3,3,57) X(1,3,4,64) X(1,4,3,73) X(1,4,4,80) \
X(2,0,2,89) X(2,1,1,94) X(2,1,2,97) X(2,1,3,102) X(2,2,0,109) X(2,2,1,110) X(2,2,2,113) \
X(2,2,3,118) X(2,2,4,125) X(2,3,1,134) X(2,3,2,137) X(2,3,3,142) X(2,3,4,149) \
X(2,4,2,158) X(2,4,3,163) X(2,4,4,170) \
X(3,0,3,179) X(3,1,2,186) X(3,1,3,191) X(3,1,4,198) X(3,2,1,207) X(3,2,2,210) \
X(3,2,3,215) X(3,2,4,222) X(3,3,0,231) X(3,3,1,232) X(3,3,2,235) X(3,3,3,240) \
X(3,3,4,247) X(3,4,1,256) X(3,4,2,259) X(3,4,3,264) X(3,4,4,271) \
X(4,0,4,280) X(4,1,3,289) X(4,1,4,296) X(4,2,2,305) X(4,2,3,310) X(4,2,4,317) \
X(4,3,1,326) X(4,3,2,329) X(4,3,3,334) X(4,3,4,341) X(4,4,0,350) X(4,4,1,351) \
X(4,4,2,354) X(4,4,3,359) X(4,4,4,366)

struct Tables {
    int   sStart[NS + 1];
    int   ijPacked[NE_MAX];   // (i<<5)|j
    float coef[NE_MAX];
};

static Tables h_tab;                 // host-side, built once at static init
__device__ Tables g_tab;             // device copy (refreshed each launch)

__device__ int g_cnt[NATOM_MAX];
__device__ int g_cursor[NATOM_MAX];
__device__ int g_off[NATOM_MAX + 1];
__device__ int g_pairIdx[NPAIR_MAX];

// ---------------------------------------------------------------------------
// Host: Clebsch-Gordan in the real spherical-harmonic basis (exact port)
// ---------------------------------------------------------------------------
static double factd(int n) { double r = 1.0; for (int i = 2; i <= n; i++) r *= (double)i; return r; }

static double cg_complex(int l1, int m1, int l2, int m2, int l3, int m3) {
    if (m1 + m2 != m3 || l3 < std::abs(l1 - l2) || l3 > l1 + l2) return 0.0;
    double pref = std::sqrt((2 * l3 + 1) * factd(l1 + l2 - l3) * factd(l1 - l2 + l3) *
                            factd(-l1 + l2 + l3) / factd(l1 + l2 + l3 + 1));
    pref *= std::sqrt(factd(l1 + m1) * factd(l1 - m1) * factd(l2 + m2) * factd(l2 - m2) *
                      factd(l3 + m3) * factd(l3 - m3));
    double s = 0.0;
    for (int k = 0; k <= l1 + l2 - l3; k++) {
        int d0 = k, d1 = l1 + l2 - l3 - k, d2 = l1 - m1 - k, d3 = l2 + m2 - k;
        int d4 = l3 - l2 + m1 + k, d5 = l3 - l1 - m2 + k;
        if (d0 < 0 || d1 < 0 || d2 < 0 || d3 < 0 || d4 < 0 || d5 < 0) continue;
        double den = factd(d0) * factd(d1) * factd(d2) * factd(d3) * factd(d4) * factd(d5);
        s += ((k & 1) ? -1.0 : 1.0) / den;
    }
    return pref * s;
}

typedef std::complex<double> cd;

static void build_tables() {
    static double CG[25][25][25];
    std::memset(CG, 0, sizeof(CG));

    static cd U[5][9][9];
    for (int l = 0; l < 5; l++) {
        for (int a = 0; a < 9; a++) for (int m = 0; m < 9; m++) U[l][a][m] = cd(0, 0);
        U[l][l][l] = cd(1, 0);
        double rs2 = 1.0 / std::sqrt(2.0);
        for (int m = 1; m <= l; m++) {
            double sgn = (m & 1) ? -1.0 : 1.0;
            U[l][l + m][l + m] = cd(sgn * rs2, 0);
            U[l][l + m][l - m] = cd(rs2, 0);
            U[l][l - m][l - m] = cd(0, rs2);
            U[l][l - m][l + m] = cd(0, -sgn * rs2);
        }
    }

    static cd cgc[9][9][9], t1[9][9][9], t2[9][9][9];
    for (int l1 = 0; l1 <= 4; l1++)
    for (int l2 = 0; l2 <= 4; l2++)
    for (int l3 = 0; l3 <= 4; l3++) {
        int n1 = 2 * l1 + 1, n2 = 2 * l2 + 1, n3 = 2 * l3 + 1;
        for (int a = 0; a < 9; a++) for (int b = 0; b < 9; b++) for (int c = 0; c < 9; c++)
            cgc[a][b][c] = cd(0, 0);
        for (int m1 = -l1; m1 <= l1; m1++)
        for (int m2 = -l2; m2 <= l2; m2++) {
            int m3 = m1 + m2;
            if (m3 >= -l3 && m3 <= l3)
                cgc[l1 + m1][l2 + m2][l3 + m3] = cd(cg_complex(l1, m1, l2, m2, l3, m3), 0);
        }
        // blk[a][b][c] = sum_{m,n,p} U1[a][m] U2[b][n] conj(U3[c][p]) cgc[m][n][p]
        for (int a = 0; a < n1; a++) for (int n = 0; n < n2; n++) for (int p = 0; p < n3; p++) {
            cd s(0, 0);
            for (int m = 0; m < n1; m++) s += U[l1][a][m] * cgc[m][n][p];
            t1[a][n][p] = s;
        }
        for (int a = 0; a < n1; a++) for (int b = 0; b < n2; b++) for (int p = 0; p < n3; p++) {
            cd s(0, 0);
            for (int n = 0; n < n2; n++) s += U[l2][b][n] * t1[a][n][p];
            t2[a][b][p] = s;
        }
        for (int a = 0; a < n1; a++) for (int b = 0; b < n2; b++) for (int c = 0; c < n3; c++) {
            cd s(0, 0);
            for (int p = 0; p < n3; p++) s += std::conj(U[l3][c][p]) * t2[a][b][p];
            CG[l1 * l1 + a][l2 * l2 + b][l3 * l3 + c] =
                (((l1 + l2 + l3) & 1) == 0) ? s.real() : s.imag();
        }
    }

    // Sparse S-tables, in TRI_LIST order (must match device TP unroll).
    int ne = 0;
#define BUILD_TRI(A, B, C, SO)                                                   \
    for (int k = 0; k < 2 * (C) + 1; k++) {                                      \
        h_tab.sStart[(SO) + k] = ne;                                             \
        for (int i = 0; i < 2 * (A) + 1; i++)                                    \
        for (int j = 0; j < 2 * (B) + 1; j++) {                                  \
            double c = CG[(A) * (A) + i][(B) * (B) + j][(C) * (C) + k];          \
            if (c > 1e-12 || c < -1e-12) {                                       \
                h_tab.ijPacked[ne] = (((A) * (A) + i) << 5) | ((B) * (B) + j);   \
                h_tab.coef[ne] = (float)c;                                       \
                ne++;                                                            \
            }                                                                    \
        }                                                                        \
    }
    TRI_LIST(BUILD_TRI)
#undef BUILD_TRI
    h_tab.sStart[NS] = ne;
}

struct TableInit { TableInit() { build_tables(); } };
static TableInit _table_init;

// ---------------------------------------------------------------------------
// Counting sort of pairs by destination atom (idx_i)
// ---------------------------------------------------------------------------
__global__ void k_zero(int nAtoms) {
    int t = blockIdx.x * blockDim.x + threadIdx.x;
    if (t < nAtoms) { g_cnt[t] = 0; g_cursor[t] = 0; }
}

__global__ void k_hist(const int* __restrict__ nbr, int nPairs) {
    int p = blockIdx.x * blockDim.x + threadIdx.x;
    if (p < nPairs) atomicAdd(&g_cnt[nbr[p]], 1);
}

__global__ void k_scan(int nAtoms) {   // nAtoms <= 2048, launch <<<1,1024>>>
    __shared__ int wsum[32];
    int t = threadIdx.x;
    int i0 = 2 * t, i1 = 2 * t + 1;
    int v0 = (i0 < nAtoms) ? g_cnt[i0] : 0;
    int v1 = (i1 < nAtoms) ? g_cnt[i1] : 0;
    int tsum = v0 + v1;
    int lane = t & 31, w = t >> 5;
    int inc = tsum;
#pragma unroll
    for (int o = 1; o < 32; o <<= 1) {
        int n = __shfl_up_sync(0xffffffffu, inc, o);
        if (lane >= o) inc += n;
    }
    if (lane == 31) wsum[w] = inc;
    __syncthreads();
    if (t < 32) {
        int ws = wsum[t], s = ws;
#pragma unroll
        for (int o = 1; o < 32; o <<= 1) {
            int n = __shfl_up_sync(0xffffffffu, s, o);
            if (t >= o) s += n;
        }
        wsum[t] = s - ws;   // exclusive warp base
    }
    __syncthreads();
    int excl = wsum[w] + (inc - tsum);
    if (i0 <= nAtoms) g_off[i0] = excl;
    if (i1 <= nAtoms) g_off[i1] = excl + v0;
    if (t == 1023) g_off[nAtoms] = excl + tsum;  // grand total (tail counts are 0)
}

__global__ void k_scatter(const int* __restrict__ nbr, int nPairs) {
    int p = blockIdx.x * blockDim.x + threadIdx.x;
    if (p < nPairs) {
        int a = nbr[p];
        int pos = g_off[a] + atomicAdd(&g_cursor[a], 1);
        g_pairIdx[pos] = p;
    }
}

// ---------------------------------------------------------------------------
// Main fused kernel: one block (64 threads) per atom; thread = feature f.
// ---------------------------------------------------------------------------
__global__ __launch_bounds__(64) void k_main(
    const int* __restrict__ Z, const float* __restrict__ disp,
    const int* __restrict__ nbr, const float* __restrict__ SE,
    const float* __restrict__ Wt, const float* __restrict__ bt,
    const float* __restrict__ W1, const float* __restrict__ b1,
    const float* __restrict__ W2, const float* __restrict__ b2,
    float* __restrict__ out, int nPairs)
{
    const int a = blockIdx.x;
    const int f = threadIdx.x;

    __shared__ float se_sh[NF];
    __shared__ float Y_sh[NP][FDIM];
    __shared__ float rad_sh[NP][NF];
    __shared__ float S_sh[NP][NS + 1];
    __shared__ float r_sh[NP], env_sh[NP];
    __shared__ int   jz_sh[NP];

    // emb[a][f] = (species_embed[Z[a]] @ Wt)[f] + bt[f]
    se_sh[f] = SE[Z[a] * NF + f];
    __syncthreads();
    float emb = bt[f];
#pragma unroll 8
    for (int g = 0; g < NF; g++) emb = fmaf(se_sh[g], Wt[g * NF + f], emb);

    const float b1f = b1[f] * 3.5449077018110318f;   // 1/Y00
    const float b2f = b2[f] * 3.5449077018110318f;

    float out_acc[FDIM];
#pragma unroll
    for (int k = 0; k < FDIM; k++) out_acc[k] = 0.0f;

    const int p0 = g_off[a], p1 = g_off[a + 1];
    const float DELTA = 5.0f / 63.0f;
    const float GC = -0.5f * 63.0f * 63.0f / 25.0f;   // -0.5/delta^2

    for (int base = p0; base < p1; base += NP) {
        const int np = min(NP, p1 - base);
        __syncthreads();

        // ---- Phase A: geometry + spherical harmonics (threads 0..np-1) ----
        if (f < np) {
            int p = g_pairIdx[base + f];
            float dx = disp[3 * p], dy = disp[3 * p + 1], dz = disp[3 * p + 2];
            float r = sqrtf(dx * dx + dy * dy + dz * dz + 1e-12f);
            float inv = 1.0f / r;
            float x = dx * inv, y = dy * inv, z = dz * inv;
            float x2 = x * x, y2 = y * y, z2 = z * z;
            float* Yv = Y_sh[f];
            Yv[0]  = 0.28209479177387814f;
            Yv[1]  = 0.4886025119029199f * y;
            Yv[2]  = 0.4886025119029199f * z;
            Yv[3]  = 0.4886025119029199f * x;
            Yv[4]  = 1.0925484305920792f * x * y;
            Yv[5]  = 1.0925484305920792f * y * z;
            Yv[6]  = 0.31539156525252005f * (3.0f * z2 - 1.0f);
            Yv[7]  = 1.0925484305920792f * x * z;
            Yv[8]  = 0.5462742152960396f * (x2 - y2);
            Yv[9]  = 0.5900435899266435f * y * (3.0f * x2 - y2);
            Yv[10] = 2.890611442640554f * x * y * z;
            Yv[11] = 0.4570457994644658f * y * (5.0f * z2 - 1.0f);
            Yv[12] = 0.3731763325901154f * z * (5.0f * z2 - 3.0f);
            Yv[13] = 0.4570457994644658f * x * (5.0f * z2 - 1.0f);
            Yv[14] = 1.445305721320277f * z * (x2 - y2);
            Yv[15] = 0.5900435899266435f * x * (x2 - 3.0f * y2);
            Yv[16] = 2.5033429417967046f * x * y * (x2 - y2);
            Yv[17] = 1.7701307697799304f * y * z * (3.0f * x2 - y2);
            Yv[18] = 0.9461746957575601f * x * y * (7.0f * z2 - 1.0f);
            Yv[19] = 0.6690465435572892f * y * z * (7.0f * z2 - 3.0f);
            Yv[20] = 0.10578554691520431f * (35.0f * z2 * z2 - 30.0f * z2 + 3.0f);
            Yv[21] = 0.6690465435572892f * x * z * (7.0f * z2 - 3.0f);
            Yv[22] = 0.47308734787878004f * (x2 - y2) * (7.0f * z2 - 1.0f);
            Yv[23] = 1.7701307697799304f * x * z * (x2 - 3.0f * y2);
            Yv[24] = 0.6258357354491761f * (x2 * x2 - 6.0f * x2 * y2 + y2 * y2);
            r_sh[f] = r;
            float tt = fminf(r * 0.2f, 1.0f);
            env_sh[f] = 0.5f * (__cosf(3.14159265358979323846f * tt) + 1.0f);
            jz_sh[f] = Z[nbr[nPairs + p]];
        }
        __syncthreads();

        // ---- Phase B: radial basis per (pair, f) ----
        for (int p = 0; p < np; p++) {
            float d = r_sh[p] - (float)f * DELTA;
            rad_sh[p][f] = __expf(GC * d * d) * env_sh[p] * SE[jz_sh[p] * NF + f];
        }

        // ---- Phase C: per-pair S tensor S[s] = sum CG_ij * Y_i * Y_j ----
        for (int p = 0; p < np; p++) {
            const float* Yv = Y_sh[p];
            for (int s = f; s < NS; s += NF) {
                float acc = 0.0f;
                int e0 = g_tab.sStart[s], e1 = g_tab.sStart[s + 1];
                for (int e = e0; e < e1; e++) {
                    int ij = g_tab.ijPacked[e];
                    acc = fmaf(g_tab.coef[e], Yv[ij >> 5] * Yv[ij & 31], acc);
                }
                S_sh[p][s] = acc;
            }
        }
        __syncthreads();

        // ---- Phase D: GEMV  RA_l[f] = sum_f' rad[f'] W[l][f'][f]  (10 l's) ----
        float acc[NP][10];
#pragma unroll
        for (int p = 0; p < NP; p++)
#pragma unroll
            for (int l = 0; l < 10; l++) acc[p][l] = 0.0f;

#pragma unroll 2
        for (int fp = 0; fp < NF; fp++) {
            float w[10];
#pragma unroll
            for (int l = 0; l < 5; l++) {
                w[l]     = W1[(l * NF + fp) * NF + f];
                w[5 + l] = W2[(l * NF + fp) * NF + f];
            }
#pragma unroll
            for (int p = 0; p < NP; p++) {
                float rv = rad_sh[p][fp];
#pragma unroll
                for (int l = 0; l < 10; l++) acc[p][l] = fmaf(rv, w[l], acc[p][l]);
            }
        }

        // ---- Phase E: tensor product, accumulated over this atom's pairs ----
#pragma unroll
        for (int p = 0; p < NP; p++) {
            if (p >= np) break;
            float ra[5], rb[5];
            ra[0] = acc[p][0] + b1f; ra[1] = acc[p][1]; ra[2] = acc[p][2];
            ra[3] = acc[p][3];       ra[4] = acc[p][4];
            rb[0] = acc[p][5] + b2f; rb[1] = acc[p][6]; rb[2] = acc[p][7];
            rb[3] = acc[p][8];       rb[4] = acc[p][9];
            const float* Sv = S_sh[p];
#define TP_TRI(L1, L2, L3, SO)                                                  \
            {                                                                   \
                float prod = ra[L1] * rb[L2];                                   \
                _Pragma("unroll")                                               \
                for (int k = 0; k < 2 * (L3) + 1; k++)                          \
                    out_acc[(L3) * (L3) + k] =                                  \
                        fmaf(Sv[(SO) + k], prod, out_acc[(L3) * (L3) + k]);     \
            }
            TRI_LIST(TP_TRI)
#undef TP_TRI
        }
    }

    // ---- Epilogue: out[a][k][f] = emb * (acc[k] + (k==0)) ----
    float* o = out + (size_t)a * FDIM * NF + f;
    o[0] = emb * (out_acc[0] + 1.0f);
#pragma unroll
    for (int k = 1; k < FDIM; k++) o[k * NF] = emb * out_acc[k];
}

// ---------------------------------------------------------------------------
// Launch
// ---------------------------------------------------------------------------
extern "C" void kernel_launch(void* const* d_in, const int* in_sizes, int n_in,
                              void* d_out, int out_size)
{
    const int*   Z    = (const int*)  d_in[0];
    const float* disp = (const float*)d_in[1];
    const int*   nbr  = (const int*)  d_in[2];
    const float* SE   = (const float*)d_in[3];
    const float* Wt   = (const float*)d_in[4];
    const float* bt   = (const float*)d_in[5];
    const float* W1   = (const float*)d_in[6];
    const float* b1   = (const float*)d_in[7];
    const float* W2   = (const float*)d_in[8];
    const float* b2   = (const float*)d_in[9];
    float* out = (float*)d_out;

    int nAtoms = in_sizes[0];
    int nPairs = in_sizes[1] / 3;
    if (nAtoms > NATOM_MAX || nPairs > NPAIR_MAX) return;

    cudaMemcpyToSymbolAsync(g_tab, &h_tab, sizeof(Tables), 0,
                            cudaMemcpyHostToDevice, 0);

    int tb = 256;
    k_zero<<<(nAtoms + tb - 1) / tb, tb>>>(nAtoms);
    k_hist<<<(nPairs + tb - 1) / tb, tb>>>(nbr, nPairs);
    k_scan<<<1, 1024>>>(nAtoms);
    k_scatter<<<(nPairs + tb - 1) / tb, tb>>>(nbr, nPairs);
    k_main<<<nAtoms, 64>>>(Z, disp, nbr, SE, Wt, bt, W1, b1, W2, b2, out, nPairs);
}

// round 3
// speedup vs baseline: 1.3908x; 1.3908x over previous
#include <cuda_runtime.h>
#include <cstring>
#include <cmath>
#include <complex>

// ---------------------------------------------------------------------------
// Problem constants (fixed by the dataset)
// ---------------------------------------------------------------------------
#define FDIM 25              // (L_MAX+1)^2
#define NF 64                // feature / radial dim
#define NS_PAD 440           // padded S entries (each triple padded to 2*l3+2)
#define NE_MAX 12288         // upper bound on CG nonzeros
#define PQ_MAX 640           // upper bound on distinct (i,j) products
#define NATOM_MAX 4096
#define NPAIR_MAX 131072
#define NP 8                 // pairs per chunk (register tile)

// 65 valid (l1,l2,l3) triples: X(l1, l2, l3, soff, idx). Padded offset = soff+idx.
#define TRI_LIST(X) \
X(0,0,0,0,0) X(0,1,1,1,1) X(0,2,2,4,2) X(0,3,3,9,3) X(0,4,4,16,4) \
X(1,0,1,25,5) X(1,1,0,28,6) X(1,1,1,29,7) X(1,1,2,32,8) X(1,2,1,37,9) X(1,2,2,40,10) X(1,2,3,45,11) \
X(1,3,2,52,12) X(1,3,3,57,13) X(1,3,4,64,14) X(1,4,3,73,15) X(1,4,4,80,16) \
X(2,0,2,89,17) X(2,1,1,94,18) X(2,1,2,97,19) X(2,1,3,102,20) X(2,2,0,109,21) X(2,2,1,110,22) \
X(2,2,2,113,23) X(2,2,3,118,24) X(2,2,4,125,25) X(2,3,1,134,26) X(2,3,2,137,27) X(2,3,3,142,28) \
X(2,3,4,149,29) X(2,4,2,158,30) X(2,4,3,163,31) X(2,4,4,170,32) \
X(3,0,3,179,33) X(3,1,2,186,34) X(3,1,3,191,35) X(3,1,4,198,36) X(3,2,1,207,37) X(3,2,2,210,38) \
X(3,2,3,215,39) X(3,2,4,222,40) X(3,3,0,231,41) X(3,3,1,232,42) X(3,3,2,235,43) X(3,3,3,240,44) \
X(3,3,4,247,45) X(3,4,1,256,46) X(3,4,2,259,47) X(3,4,3,264,48) X(3,4,4,271,49) \
X(4,0,4,280,50) X(4,1,3,289,51) X(4,1,4,296,52) X(4,2,2,305,53) X(4,2,3,310,54) X(4,2,4,317,55) \
X(4,3,1,326,56) X(4,3,2,329,57) X(4,3,3,334,58) X(4,3,4,341,59) X(4,4,0,350,60) X(4,4,1,351,61) \
X(4,4,2,354,62) X(4,4,3,359,63) X(4,4,4,366,64)

struct Tables {
    int rowStart[NS_PAD + 1];
    int rowOrder[448];
    int pairIJ[PQ_MAX];
    int npq;
    int _pad;                       // keep ent[] 8-byte aligned
    unsigned long long ent[NE_MAX]; // (coef_bits << 32) | q
};

static Tables h_tab;
static size_t h_tab_bytes = 0;
__device__ Tables g_tab;

__device__ float2 g_Wpair[5 * NF * NF];   // [q][fp][f] -> {slot2q, slot2q+1}

__device__ int g_cnt[NATOM_MAX];
__device__ int g_cursor[NATOM_MAX];
__device__ int g_off[NATOM_MAX + 1];
__device__ int g_pairIdx[NPAIR_MAX];

// ---------------------------------------------------------------------------
// Host: Clebsch-Gordan in the real spherical-harmonic basis (exact port)
// ---------------------------------------------------------------------------
static double factd(int n) { double r = 1.0; for (int i = 2; i <= n; i++) r *= (double)i; return r; }

static double cg_complex(int l1, int m1, int l2, int m2, int l3, int m3) {
    if (m1 + m2 != m3 || l3 < std::abs(l1 - l2) || l3 > l1 + l2) return 0.0;
    double pref = std::sqrt((2 * l3 + 1) * factd(l1 + l2 - l3) * factd(l1 - l2 + l3) *
                            factd(-l1 + l2 + l3) / factd(l1 + l2 + l3 + 1));
    pref *= std::sqrt(factd(l1 + m1) * factd(l1 - m1) * factd(l2 + m2) * factd(l2 - m2) *
                      factd(l3 + m3) * factd(l3 - m3));
    double s = 0.0;
    for (int k = 0; k <= l1 + l2 - l3; k++) {
        int d0 = k, d1 = l1 + l2 - l3 - k, d2 = l1 - m1 - k, d3 = l2 + m2 - k;
        int d4 = l3 - l2 + m1 + k, d5 = l3 - l1 - m2 + k;
        if (d0 < 0 || d1 < 0 || d2 < 0 || d3 < 0 || d4 < 0 || d5 < 0) continue;
        double den = factd(d0) * factd(d1) * factd(d2) * factd(d3) * factd(d4) * factd(d5);
        s += ((k & 1) ? -1.0 : 1.0) / den;
    }
    return pref * s;
}

typedef std::complex<double> cd;

static void build_tables() {
    static double CG[25][25][25];
    std::memset(CG, 0, sizeof(CG));

    static cd U[5][9][9];
    for (int l = 0; l < 5; l++) {
        for (int a = 0; a < 9; a++) for (int m = 0; m < 9; m++) U[l][a][m] = cd(0, 0);
        U[l][l][l] = cd(1, 0);
        double rs2 = 1.0 / std::sqrt(2.0);
        for (int m = 1; m <= l; m++) {
            double sgn = (m & 1) ? -1.0 : 1.0;
            U[l][l + m][l + m] = cd(sgn * rs2, 0);
            U[l][l + m][l - m] = cd(rs2, 0);
            U[l][l - m][l - m] = cd(0, rs2);
            U[l][l - m][l + m] = cd(0, -sgn * rs2);
        }
    }

    static cd cgc[9][9][9], t1[9][9][9], t2[9][9][9];
    for (int l1 = 0; l1 <= 4; l1++)
    for (int l2 = 0; l2 <= 4; l2++)
    for (int l3 = 0; l3 <= 4; l3++) {
        int n1 = 2 * l1 + 1, n2 = 2 * l2 + 1, n3 = 2 * l3 + 1;
        for (int a = 0; a < 9; a++) for (int b = 0; b < 9; b++) for (int c = 0; c < 9; c++)
            cgc[a][b][c] = cd(0, 0);
        for (int m1 = -l1; m1 <= l1; m1++)
        for (int m2 = -l2; m2 <= l2; m2++) {
            int m3 = m1 + m2;
            if (m3 >= -l3 && m3 <= l3)
                cgc[l1 + m1][l2 + m2][l3 + m3] = cd(cg_complex(l1, m1, l2, m2, l3, m3), 0);
        }
        for (int a = 0; a < n1; a++) for (int n = 0; n < n2; n++) for (int p = 0; p < n3; p++) {
            cd s(0, 0);
            for (int m = 0; m < n1; m++) s += U[l1][a][m] * cgc[m][n][p];
            t1[a][n][p] = s;
        }
        for (int a = 0; a < n1; a++) for (int b = 0; b < n2; b++) for (int p = 0; p < n3; p++) {
            cd s(0, 0);
            for (int n = 0; n < n2; n++) s += U[l2][b][n] * t1[a][n][p];
            t2[a][b][p] = s;
        }
        for (int a = 0; a < n1; a++) for (int b = 0; b < n2; b++) for (int c = 0; c < n3; c++) {
            cd s(0, 0);
            for (int p = 0; p < n3; p++) s += std::conj(U[l3][c][p]) * t2[a][b][p];
            CG[l1 * l1 + a][l2 * l2 + b][l3 * l3 + c] =
                (((l1 + l2 + l3) & 1) == 0) ? s.real() : s.imag();
        }
    }

    // distinct-product map + padded CSR rows
    h_tab.npq = 0;
    int ne = 0;

#define BUILD_TRI(A, B, C, SO, IDX)                                              \
    {                                                                            \
        int pso = (SO) + (IDX);                                                  \
        for (int slot = 0; slot < 2 * (C) + 2; slot++) {                         \
            int row = pso + slot;                                                \
            h_tab.rowStart[row] = ne;                                            \
            int k = ((C) & 1) ? (slot - 1) : slot;                               \
            if (k >= 0 && k < 2 * (C) + 1) {                                     \
                for (int i = 0; i < 2 * (A) + 1; i++)                            \
                for (int j = 0; j < 2 * (B) + 1; j++) {                          \
                    double c = CG[(A)*(A)+i][(B)*(B)+j][(C)*(C)+k];              \
                    if (c > 1e-12 || c < -1e-12) {                               \
                        int ij = (((A)*(A)+i) << 5) | ((B)*(B)+j);               \
                        int q = -1;                                              \
                        for (int t = 0; t < h_tab.npq; t++)                      \
                            if (h_tab.pairIJ[t] == ij) { q = t; break; }         \
                        if (q < 0) { q = h_tab.npq; h_tab.pairIJ[h_tab.npq++] = ij; } \
                        float cf = (float)c;                                     \
                        unsigned int bits;                                       \
                        std::memcpy(&bits, &cf, 4);                              \
                        if (ne < NE_MAX)                                         \
                            h_tab.ent[ne++] = ((unsigned long long)bits << 32) | \
                                              (unsigned long long)(unsigned)q;   \
                    }                                                            \
                }                                                                \
            }                                                                    \
        }                                                                        \
    }
    TRI_LIST(BUILD_TRI)
#undef BUILD_TRI
    h_tab.rowStart[NS_PAD] = ne;

    // length-sorted round-robin row order (balances warp divergence)
    int order[NS_PAD];
    for (int r = 0; r < NS_PAD; r++) order[r] = r;
    for (int a = 0; a < NS_PAD; a++)          // simple selection sort, desc length
        for (int b = a + 1; b < NS_PAD; b++) {
            int la = h_tab.rowStart[order[a] + 1] - h_tab.rowStart[order[a]];
            int lb = h_tab.rowStart[order[b] + 1] - h_tab.rowStart[order[b]];
            if (lb > la) { int t = order[a]; order[a] = order[b]; order[b] = t; }
        }
    for (int p = 0; p < 448; p++) h_tab.rowOrder[p] = (p < NS_PAD) ? order[p] : -1;

    h_tab_bytes = (size_t)((char*)&h_tab.ent[ne] - (char*)&h_tab);
}

struct TableInit { TableInit() { build_tables(); } };
static TableInit _table_init;

// ---------------------------------------------------------------------------
// packed f32x2 FMA (ptxas never emits FFMA2 from C++)
// ---------------------------------------------------------------------------
__device__ __forceinline__ void ffma2(float2& d, const float2& a, const float2& b) {
    asm("fma.rn.f32x2 %0, %1, %2, %0;"
        : "+l"(*reinterpret_cast<unsigned long long*>(&d))
        : "l"(*reinterpret_cast<const unsigned long long*>(&a)),
          "l"(*reinterpret_cast<const unsigned long long*>(&b)));
}

// ---------------------------------------------------------------------------
// Counting sort of pairs by destination atom (idx_i)
// ---------------------------------------------------------------------------
__global__ void k_zero(int nAtoms) {
    int t = blockIdx.x * blockDim.x + threadIdx.x;
    if (t < nAtoms) { g_cnt[t] = 0; g_cursor[t] = 0; }
}

__global__ void k_hist(const int* __restrict__ nbr, int nPairs) {
    int p = blockIdx.x * blockDim.x + threadIdx.x;
    if (p < nPairs) atomicAdd(&g_cnt[nbr[p]], 1);
}

__global__ void k_scan(int nAtoms) {   // nAtoms <= 2048, launch <<<1,1024>>>
    __shared__ int wsum[32];
    int t = threadIdx.x;
    int i0 = 2 * t, i1 = 2 * t + 1;
    int v0 = (i0 < nAtoms) ? g_cnt[i0] : 0;
    int v1 = (i1 < nAtoms) ? g_cnt[i1] : 0;
    int tsum = v0 + v1;
    int lane = t & 31, w = t >> 5;
    int inc = tsum;
#pragma unroll
    for (int o = 1; o < 32; o <<= 1) {
        int n = __shfl_up_sync(0xffffffffu, inc, o);
        if (lane >= o) inc += n;
    }
    if (lane == 31) wsum[w] = inc;
    __syncthreads();
    if (t < 32) {
        int ws = wsum[t], s = ws;
#pragma unroll
        for (int o = 1; o < 32; o <<= 1) {
            int n = __shfl_up_sync(0xffffffffu, s, o);
            if (t >= o) s += n;
        }
        wsum[t] = s - ws;
    }
    __syncthreads();
    int excl = wsum[w] + (inc - tsum);
    if (i0 <= nAtoms) g_off[i0] = excl;
    if (i1 <= nAtoms) g_off[i1] = excl + v0;
    if (t == 1023) g_off[nAtoms] = excl + tsum;
}

__global__ void k_scatter(const int* __restrict__ nbr, int nPairs) {
    int p = blockIdx.x * blockDim.x + threadIdx.x;
    if (p < nPairs) {
        int a = nbr[p];
        int pos = g_off[a] + atomicAdd(&g_cursor[a], 1);
        g_pairIdx[pos] = p;
    }
}

// ---------------------------------------------------------------------------
// W1/W2 -> packed scratch: Wpair[q][fp][f] = {slot(2q)[fp][f], slot(2q+1)[fp][f]}
// slot l<5 -> W1[l], else W2[l-5]
// ---------------------------------------------------------------------------
__global__ void k_wpack(const float* __restrict__ W1, const float* __restrict__ W2) {
    int t = blockIdx.x * blockDim.x + threadIdx.x;
    if (t >= 5 * NF * NF) return;
    int f = t & 63, fp = (t >> 6) & 63, q = t >> 12;
    int s0 = 2 * q, s1 = 2 * q + 1;
    float a = (s0 < 5) ? W1[(s0 * NF + fp) * NF + f] : W2[((s0 - 5) * NF + fp) * NF + f];
    float b = (s1 < 5) ? W1[(s1 * NF + fp) * NF + f] : W2[((s1 - 5) * NF + fp) * NF + f];
    g_Wpair[t] = make_float2(a, b);
}

// ---------------------------------------------------------------------------
// Main fused kernel: one block (64 threads) per atom; thread = feature f.
// ---------------------------------------------------------------------------
__global__ __launch_bounds__(64) void k_main(
    const int* __restrict__ Z, const float* __restrict__ disp,
    const int* __restrict__ nbr, const float* __restrict__ SE,
    const float* __restrict__ Wt, const float* __restrict__ bt,
    const float* __restrict__ b1, const float* __restrict__ b2,
    float* __restrict__ out, int nPairs)
{
    const int a = blockIdx.x;
    const int f = threadIdx.x;

    __shared__ float  se_sh[NF];
    __shared__ float  Y_sh[NP][26];
    __shared__ float2 rad2_sh[NP][NF];
    __shared__ float  S_sh[NP][NS_PAD];
    __shared__ float  P_sh[NP][PQ_MAX];
    __shared__ float  r_sh[NP], env_sh[NP];
    __shared__ int    jz_sh[NP];

    // emb[a][f] = (species_embed[Z[a]] @ Wt)[f] + bt[f]
    se_sh[f] = SE[Z[a] * NF + f];
    __syncthreads();
    float emb = bt[f];
#pragma unroll 8
    for (int g = 0; g < NF; g++) emb = fmaf(se_sh[g], Wt[g * NF + f], emb);

    const float b1f = b1[f] * 3.5449077018110318f;   // 1/Y00
    const float b2f = b2[f] * 3.5449077018110318f;

    float2 oa[13];
#pragma unroll
    for (int k = 0; k < 13; k++) oa[k] = make_float2(0.0f, 0.0f);

    const int p0 = g_off[a], p1 = g_off[a + 1];
    const float DELTA = 5.0f / 63.0f;
    const float GC = -0.5f * 63.0f * 63.0f / 25.0f;
    const int npq = g_tab.npq;

    for (int base = p0; base < p1; base += NP) {
        const int np = min(NP, p1 - base);
        __syncthreads();

        // ---- Phase A: geometry + spherical harmonics (threads 0..np-1) ----
        if (f < np) {
            int p = g_pairIdx[base + f];
            float dx = disp[3 * p], dy = disp[3 * p + 1], dz = disp[3 * p + 2];
            float r = sqrtf(dx * dx + dy * dy + dz * dz + 1e-12f);
            float inv = 1.0f / r;
            float x = dx * inv, y = dy * inv, z = dz * inv;
            float x2 = x * x, y2 = y * y, z2 = z * z;
            float* Yv = Y_sh[f];
            Yv[0]  = 0.28209479177387814f;
            Yv[1]  = 0.4886025119029199f * y;
            Yv[2]  = 0.4886025119029199f * z;
            Yv[3]  = 0.4886025119029199f * x;
            Yv[4]  = 1.0925484305920792f * x * y;
            Yv[5]  = 1.0925484305920792f * y * z;
            Yv[6]  = 0.31539156525252005f * (3.0f * z2 - 1.0f);
            Yv[7]  = 1.0925484305920792f * x * z;
            Yv[8]  = 0.5462742152960396f * (x2 - y2);
            Yv[9]  = 0.5900435899266435f * y * (3.0f * x2 - y2);
            Yv[10] = 2.890611442640554f * x * y * z;
            Yv[11] = 0.4570457994644658f * y * (5.0f * z2 - 1.0f);
            Yv[12] = 0.3731763325901154f * z * (5.0f * z2 - 3.0f);
            Yv[13] = 0.4570457994644658f * x * (5.0f * z2 - 1.0f);
            Yv[14] = 1.445305721320277f * z * (x2 - y2);
            Yv[15] = 0.5900435899266435f * x * (x2 - 3.0f * y2);
            Yv[16] = 2.5033429417967046f * x * y * (x2 - y2);
            Yv[17] = 1.7701307697799304f * y * z * (3.0f * x2 - y2);
            Yv[18] = 0.9461746957575601f * x * y * (7.0f * z2 - 1.0f);
            Yv[19] = 0.6690465435572892f * y * z * (7.0f * z2 - 3.0f);
            Yv[20] = 0.10578554691520431f * (35.0f * z2 * z2 - 30.0f * z2 + 3.0f);
            Yv[21] = 0.6690465435572892f * x * z * (7.0f * z2 - 3.0f);
            Yv[22] = 0.47308734787878004f * (x2 - y2) * (7.0f * z2 - 1.0f);
            Yv[23] = 1.7701307697799304f * x * z * (x2 - 3.0f * y2);
            Yv[24] = 0.6258357354491761f * (x2 * x2 - 6.0f * x2 * y2 + y2 * y2);
            r_sh[f] = r;
            float tt = fminf(r * 0.2f, 1.0f);
            env_sh[f] = 0.5f * (__cosf(3.14159265358979323846f * tt) + 1.0f);
            jz_sh[f] = Z[nbr[nPairs + p]];
        }
        __syncthreads();

        // ---- Phase B: radial basis, duplicated for packed broadcast ----
        for (int p = 0; p < np; p++) {
            float d = r_sh[p] - (float)f * DELTA;
            float v = __expf(GC * d * d) * env_sh[p] * SE[jz_sh[p] * NF + f];
            rad2_sh[p][f] = make_float2(v, v);
        }

        // ---- Phase C1: distinct products P[q] = Y_i * Y_j ----
        for (int q = f; q < npq; q += NF) {
            int ij = g_tab.pairIJ[q];
            float yi[NP];
#pragma unroll
            for (int p = 0; p < NP; p++) yi[p] = Y_sh[p][ij >> 5] * Y_sh[p][ij & 31];
#pragma unroll
            for (int p = 0; p < NP; p++) P_sh[p][q] = yi[p];
        }
        __syncthreads();

        // ---- Phase C2: padded S rows, entry table amortized over 8 pairs ----
        for (int t = 0; t < 7; t++) {
            int pos = t * NF + f;
            if (pos >= NS_PAD) break;
            int row = g_tab.rowOrder[pos];
            int e0 = g_tab.rowStart[row], e1 = g_tab.rowStart[row + 1];
            float acc[NP];
#pragma unroll
            for (int p = 0; p < NP; p++) acc[p] = 0.0f;
            for (int e = e0; e < e1; e++) {
                unsigned long long v = g_tab.ent[e];
                int q = (int)(unsigned int)v;
                float c = __int_as_float((int)(v >> 32));
#pragma unroll
                for (int p = 0; p < NP; p++) acc[p] = fmaf(c, P_sh[p][q], acc[p]);
            }
#pragma unroll
            for (int p = 0; p < NP; p++) S_sh[p][row] = acc[p];
        }
        __syncthreads();

        // ---- Phase D: packed GEMV  acc2[p][q] = sum_fp rad[p][fp] * Wpair[q][fp][f]
        float2 acc2[NP][5];
#pragma unroll
        for (int p = 0; p < NP; p++)
#pragma unroll
            for (int q = 0; q < 5; q++) acc2[p][q] = make_float2(0.0f, 0.0f);

#pragma unroll 2
        for (int fp = 0; fp < NF; fp++) {
            float2 w[5];
#pragma unroll
            for (int q = 0; q < 5; q++) w[q] = g_Wpair[(q * NF + fp) * NF + f];
#pragma unroll
            for (int p = 0; p < NP; p++) {
                float2 rv2 = rad2_sh[p][fp];
#pragma unroll
                for (int q = 0; q < 5; q++) ffma2(acc2[p][q], rv2, w[q]);
            }
        }

        // ---- Phase E: packed tensor product ----
#pragma unroll
        for (int p = 0; p < NP; p++) {
            if (p >= np) break;
            float ra[5], rb[5];
            ra[0] = acc2[p][0].x + b1f; ra[1] = acc2[p][0].y;
            ra[2] = acc2[p][1].x;       ra[3] = acc2[p][1].y;
            ra[4] = acc2[p][2].x;
            rb[0] = acc2[p][2].y + b2f; rb[1] = acc2[p][3].x;
            rb[2] = acc2[p][3].y;       rb[3] = acc2[p][4].x;
            rb[4] = acc2[p][4].y;
            const float* Sp = S_sh[p];
#define TP_TRI(L1, L2, L3, SO, IDX)                                             \
            {                                                                   \
                float prod = ra[L1] * rb[L2];                                   \
                float2 pr2 = make_float2(prod, prod);                           \
                _Pragma("unroll")                                               \
                for (int t = 0; t <= (L3); t++)                                 \
                    ffma2(oa[((L3) * (L3)) / 2 + t], pr2,                       \
                          *(const float2*)(Sp + (SO) + (IDX) + 2 * t));         \
            }
            TRI_LIST(TP_TRI)
#undef TP_TRI
        }
    }

    // ---- Epilogue: out[a][k][f] = emb * (acc[k] + (k==0)) ----
    float* o = out + (size_t)a * FDIM * NF + f;
    oa[0].x += 1.0f;
#pragma unroll
    for (int t = 0; t < 12; t++) {
        o[(2 * t) * NF]     = emb * oa[t].x;
        o[(2 * t + 1) * NF] = emb * oa[t].y;
    }
    o[24 * NF] = emb * oa[12].x;
}

// ---------------------------------------------------------------------------
// Launch
// ---------------------------------------------------------------------------
extern "C" void kernel_launch(void* const* d_in, const int* in_sizes, int n_in,
                              void* d_out, int out_size)
{
    const int*   Z    = (const int*)  d_in[0];
    const float* disp = (const float*)d_in[1];
    const int*   nbr  = (const int*)  d_in[2];
    const float* SE   = (const float*)d_in[3];
    const float* Wt   = (const float*)d_in[4];
    const float* bt   = (const float*)d_in[5];
    const float* W1   = (const float*)d_in[6];
    const float* b1   = (const float*)d_in[7];
    const float* W2   = (const float*)d_in[8];
    const float* b2   = (const float*)d_in[9];
    float* out = (float*)d_out;

    int nAtoms = in_sizes[0];
    int nPairs = in_sizes[1] / 3;
    if (nAtoms > NATOM_MAX || nPairs > NPAIR_MAX) return;

    cudaMemcpyToSymbolAsync(g_tab, &h_tab, h_tab_bytes, 0,
                            cudaMemcpyHostToDevice, 0);

    int tb = 256;
    k_wpack<<<(5 * NF * NF + tb - 1) / tb, tb>>>(W1, W2);
    k_zero<<<(nAtoms + tb - 1) / tb, tb>>>(nAtoms);
    k_hist<<<(nPairs + tb - 1) / tb, tb>>>(nbr, nPairs);
    k_scan<<<1, 1024>>>(nAtoms);
    k_scatter<<<(nPairs + tb - 1) / tb, tb>>>(nbr, nPairs);
    k_main<<<nAtoms, 64>>>(Z, disp, nbr, SE, Wt, bt, b1, b2, out, nPairs);
}

// round 4
// speedup vs baseline: 1.7189x; 1.2359x over previous
#include <cuda_runtime.h>
#include <cstring>
#include <cmath>
#include <complex>

// ---------------------------------------------------------------------------
// Problem constants (fixed by the dataset)
// ---------------------------------------------------------------------------
#define FDIM 25              // (L_MAX+1)^2
#define NF 64                // feature / radial dim
#define NS_PAD 440           // padded S entries (each triple padded to 2*l3+2)
#define NE_MAX 12288         // upper bound on CG nonzeros
#define NATOM_MAX 4096
#define NPAIR_MAX 65536
#define NP 8                 // pairs per chunk (register tile)
#define NSLOT2 5             // 10 l-slots packed as 5 float2

// 65 valid (l1,l2,l3) triples: X(l1, l2, l3, soff, idx). Padded offset = soff+idx.
#define TRI_LIST(X) \
X(0,0,0,0,0) X(0,1,1,1,1) X(0,2,2,4,2) X(0,3,3,9,3) X(0,4,4,16,4) \
X(1,0,1,25,5) X(1,1,0,28,6) X(1,1,1,29,7) X(1,1,2,32,8) X(1,2,1,37,9) X(1,2,2,40,10) X(1,2,3,45,11) \
X(1,3,2,52,12) X(1,3,3,57,13) X(1,3,4,64,14) X(1,4,3,73,15) X(1,4,4,80,16) \
X(2,0,2,89,17) X(2,1,1,94,18) X(2,1,2,97,19) X(2,1,3,102,20) X(2,2,0,109,21) X(2,2,1,110,22) \
X(2,2,2,113,23) X(2,2,3,118,24) X(2,2,4,125,25) X(2,3,1,134,26) X(2,3,2,137,27) X(2,3,3,142,28) \
X(2,3,4,149,29) X(2,4,2,158,30) X(2,4,3,163,31) X(2,4,4,170,32) \
X(3,0,3,179,33) X(3,1,2,186,34) X(3,1,3,191,35) X(3,1,4,198,36) X(3,2,1,207,37) X(3,2,2,210,38) \
X(3,2,3,215,39) X(3,2,4,222,40) X(3,3,0,231,41) X(3,3,1,232,42) X(3,3,2,235,43) X(3,3,3,240,44) \
X(3,3,4,247,45) X(3,4,1,256,46) X(3,4,2,259,47) X(3,4,3,264,48) X(3,4,4,271,49) \
X(4,0,4,280,50) X(4,1,3,289,51) X(4,1,4,296,52) X(4,2,2,305,53) X(4,2,3,310,54) X(4,2,4,317,55) \
X(4,3,1,326,56) X(4,3,2,329,57) X(4,3,3,334,58) X(4,3,4,341,59) X(4,4,0,350,60) X(4,4,1,351,61) \
X(4,4,2,354,62) X(4,4,3,359,63) X(4,4,4,366,64)

struct Tables {
    int rowStart[NS_PAD + 1];
    int rowOrder[448];
    int _pad;
    unsigned long long ent[NE_MAX]; // (coef_bits << 32) | (i<<5) | j
};

static Tables h_tab;
static size_t h_tab_bytes = 0;
__device__ Tables g_tab;

__device__ float2 g_Wpair[5 * NF * NF];          // [q][fp][f] -> {slot2q, slot2q+1}
__device__ float2 g_RAB[(size_t)NPAIR_MAX * 320]; // [pair][q(5)][f(64)]

__device__ float2 g_rEnv[NPAIR_MAX];
__device__ int    g_jz[NPAIR_MAX];
__device__ int    g_cB[NPAIR_MAX];

__device__ int g_cnt[NATOM_MAX];
__device__ int g_cursor[NATOM_MAX];
__device__ int g_off[NATOM_MAX + 1];
__device__ int g_pairIdx[NPAIR_MAX];

__device__ int g_cntR[64];
__device__ int g_curR[64];
__device__ int g_offR[65];
__device__ int g_pairIdxR[NPAIR_MAX];

// ---------------------------------------------------------------------------
// Host: Clebsch-Gordan in the real spherical-harmonic basis (exact port)
// ---------------------------------------------------------------------------
static double factd(int n) { double r = 1.0; for (int i = 2; i <= n; i++) r *= (double)i; return r; }

static double cg_complex(int l1, int m1, int l2, int m2, int l3, int m3) {
    if (m1 + m2 != m3 || l3 < std::abs(l1 - l2) || l3 > l1 + l2) return 0.0;
    double pref = std::sqrt((2 * l3 + 1) * factd(l1 + l2 - l3) * factd(l1 - l2 + l3) *
                            factd(-l1 + l2 + l3) / factd(l1 + l2 + l3 + 1));
    pref *= std::sqrt(factd(l1 + m1) * factd(l1 - m1) * factd(l2 + m2) * factd(l2 - m2) *
                      factd(l3 + m3) * factd(l3 - m3));
    double s = 0.0;
    for (int k = 0; k <= l1 + l2 - l3; k++) {
        int d0 = k, d1 = l1 + l2 - l3 - k, d2 = l1 - m1 - k, d3 = l2 + m2 - k;
        int d4 = l3 - l2 + m1 + k, d5 = l3 - l1 - m2 + k;
        if (d0 < 0 || d1 < 0 || d2 < 0 || d3 < 0 || d4 < 0 || d5 < 0) continue;
        double den = factd(d0) * factd(d1) * factd(d2) * factd(d3) * factd(d4) * factd(d5);
        s += ((k & 1) ? -1.0 : 1.0) / den;
    }
    return pref * s;
}

typedef std::complex<double> cd;

static void build_tables() {
    static double CG[25][25][25];
    std::memset(CG, 0, sizeof(CG));

    static cd U[5][9][9];
    for (int l = 0; l < 5; l++) {
        for (int a = 0; a < 9; a++) for (int m = 0; m < 9; m++) U[l][a][m] = cd(0, 0);
        U[l][l][l] = cd(1, 0);
        double rs2 = 1.0 / std::sqrt(2.0);
        for (int m = 1; m <= l; m++) {
            double sgn = (m & 1) ? -1.0 : 1.0;
            U[l][l + m][l + m] = cd(sgn * rs2, 0);
            U[l][l + m][l - m] = cd(rs2, 0);
            U[l][l - m][l - m] = cd(0, rs2);
            U[l][l - m][l + m] = cd(0, -sgn * rs2);
        }
    }

    static cd cgc[9][9][9], t1[9][9][9], t2[9][9][9];
    for (int l1 = 0; l1 <= 4; l1++)
    for (int l2 = 0; l2 <= 4; l2++)
    for (int l3 = 0; l3 <= 4; l3++) {
        int n1 = 2 * l1 + 1, n2 = 2 * l2 + 1, n3 = 2 * l3 + 1;
        for (int a = 0; a < 9; a++) for (int b = 0; b < 9; b++) for (int c = 0; c < 9; c++)
            cgc[a][b][c] = cd(0, 0);
        for (int m1 = -l1; m1 <= l1; m1++)
        for (int m2 = -l2; m2 <= l2; m2++) {
            int m3 = m1 + m2;
            if (m3 >= -l3 && m3 <= l3)
                cgc[l1 + m1][l2 + m2][l3 + m3] = cd(cg_complex(l1, m1, l2, m2, l3, m3), 0);
        }
        for (int a = 0; a < n1; a++) for (int n = 0; n < n2; n++) for (int p = 0; p < n3; p++) {
            cd s(0, 0);
            for (int m = 0; m < n1; m++) s += U[l1][a][m] * cgc[m][n][p];
            t1[a][n][p] = s;
        }
        for (int a = 0; a < n1; a++) for (int b = 0; b < n2; b++) for (int p = 0; p < n3; p++) {
            cd s(0, 0);
            for (int n = 0; n < n2; n++) s += U[l2][b][n] * t1[a][n][p];
            t2[a][b][p] = s;
        }
        for (int a = 0; a < n1; a++) for (int b = 0; b < n2; b++) for (int c = 0; c < n3; c++) {
            cd s(0, 0);
            for (int p = 0; p < n3; p++) s += std::conj(U[l3][c][p]) * t2[a][b][p];
            CG[l1 * l1 + a][l2 * l2 + b][l3 * l3 + c] =
                (((l1 + l2 + l3) & 1) == 0) ? s.real() : s.imag();
        }
    }

    int ne = 0;
#define BUILD_TRI(A, B, C, SO, IDX)                                              \
    {                                                                            \
        int pso = (SO) + (IDX);                                                  \
        for (int slot = 0; slot < 2 * (C) + 2; slot++) {                         \
            int row = pso + slot;                                                \
            h_tab.rowStart[row] = ne;                                            \
            int k = ((C) & 1) ? (slot - 1) : slot;                               \
            if (k >= 0 && k < 2 * (C) + 1) {                                     \
                for (int i = 0; i < 2 * (A) + 1; i++)                            \
                for (int j = 0; j < 2 * (B) + 1; j++) {                          \
                    double c = CG[(A)*(A)+i][(B)*(B)+j][(C)*(C)+k];              \
                    if (c > 1e-12 || c < -1e-12) {                               \
                        int ij = (((A)*(A)+i) << 5) | ((B)*(B)+j);               \
                        float cf = (float)c;                                     \
                        unsigned int bits;                                       \
                        std::memcpy(&bits, &cf, 4);                              \
                        if (ne < NE_MAX)                                         \
                            h_tab.ent[ne++] = ((unsigned long long)bits << 32) | \
                                              (unsigned long long)(unsigned)ij;  \
                    }                                                            \
                }                                                                \
            }                                                                    \
        }                                                                        \
    }
    TRI_LIST(BUILD_TRI)
#undef BUILD_TRI
    h_tab.rowStart[NS_PAD] = ne;

    // length-sorted round-robin row order (balances warp divergence)
    int order[NS_PAD];
    for (int r = 0; r < NS_PAD; r++) order[r] = r;
    for (int a = 0; a < NS_PAD; a++)
        for (int b = a + 1; b < NS_PAD; b++) {
            int la = h_tab.rowStart[order[a] + 1] - h_tab.rowStart[order[a]];
            int lb = h_tab.rowStart[order[b] + 1] - h_tab.rowStart[order[b]];
            if (lb > la) { int t = order[a]; order[a] = order[b]; order[b] = t; }
        }
    for (int p = 0; p < 448; p++) h_tab.rowOrder[p] = (p < NS_PAD) ? order[p] : -1;

    h_tab_bytes = (size_t)((char*)&h_tab.ent[ne] - (char*)&h_tab);
}

struct TableInit { TableInit() { build_tables(); } };
static TableInit _table_init;

// ---------------------------------------------------------------------------
// packed f32x2 FMA (ptxas never emits FFMA2 from C++)
// ---------------------------------------------------------------------------
__device__ __forceinline__ void ffma2(float2& d, const float2& a, const float2& b) {
    asm("fma.rn.f32x2 %0, %1, %2, %0;"
        : "+l"(*reinterpret_cast<unsigned long long*>(&d))
        : "l"(*reinterpret_cast<const unsigned long long*>(&a)),
          "l"(*reinterpret_cast<const unsigned long long*>(&b)));
}

// ---------------------------------------------------------------------------
// Prep: geometry scalars + histograms (atom and radius-bucket)
// ---------------------------------------------------------------------------
__global__ void k_zero(int nAtoms) {
    int t = blockIdx.x * blockDim.x + threadIdx.x;
    if (t < nAtoms) { g_cnt[t] = 0; g_cursor[t] = 0; }
    if (t < 64)     { g_cntR[t] = 0; g_curR[t] = 0; }
}

__global__ void k_prep(const float* __restrict__ disp, const int* __restrict__ nbr,
                       const int* __restrict__ Z, int nPairs) {
    int p = blockIdx.x * blockDim.x + threadIdx.x;
    if (p >= nPairs) return;
    float dx = disp[3 * p], dy = disp[3 * p + 1], dz = disp[3 * p + 2];
    float r = sqrtf(dx * dx + dy * dy + dz * dz + 1e-12f);
    float tt = fminf(r * 0.2f, 1.0f);
    float env = 0.5f * (__cosf(3.14159265358979323846f * tt) + 1.0f);
    g_rEnv[p] = make_float2(r, env);
    g_jz[p] = Z[nbr[nPairs + p]];
    int c = (int)(r * (63.0f / 5.0f));
    c = min(63, max(0, c));
    g_cB[p] = c;
    atomicAdd(&g_cnt[nbr[p]], 1);
    atomicAdd(&g_cntR[c], 1);
}

__global__ void k_scan(int nAtoms) {   // <<<1,1024>>>
    __shared__ int wsum[32];
    int t = threadIdx.x;
    if (t == 0) {   // radius-bucket exclusive scan (64 values, trivial)
        int s = 0;
        for (int b = 0; b < 64; b++) { g_offR[b] = s; s += g_cntR[b]; }
        g_offR[64] = s;
    }
    int i0 = 2 * t, i1 = 2 * t + 1;
    int v0 = (i0 < nAtoms) ? g_cnt[i0] : 0;
    int v1 = (i1 < nAtoms) ? g_cnt[i1] : 0;
    int tsum = v0 + v1;
    int lane = t & 31, w = t >> 5;
    int inc = tsum;
#pragma unroll
    for (int o = 1; o < 32; o <<= 1) {
        int n = __shfl_up_sync(0xffffffffu, inc, o);
        if (lane >= o) inc += n;
    }
    if (lane == 31) wsum[w] = inc;
    __syncthreads();
    if (t < 32) {
        int ws = wsum[t], s = ws;
#pragma unroll
        for (int o = 1; o < 32; o <<= 1) {
            int n = __shfl_up_sync(0xffffffffu, s, o);
            if (t >= o) s += n;
        }
        wsum[t] = s - ws;
    }
    __syncthreads();
    int excl = wsum[w] + (inc - tsum);
    if (i0 <= nAtoms) g_off[i0] = excl;
    if (i1 <= nAtoms) g_off[i1] = excl + v0;
    if (t == 1023) g_off[nAtoms] = excl + tsum;
}

__global__ void k_scatter(const int* __restrict__ nbr, int nPairs) {
    int p = blockIdx.x * blockDim.x + threadIdx.x;
    if (p < nPairs) {
        int a = nbr[p];
        g_pairIdx[g_off[a] + atomicAdd(&g_cursor[a], 1)] = p;
        int c = g_cB[p];
        g_pairIdxR[g_offR[c] + atomicAdd(&g_curR[c], 1)] = p;
    }
}

// ---------------------------------------------------------------------------
// W1/W2 -> packed scratch: Wpair[q][fp][f] = {slot(2q)[fp][f], slot(2q+1)[fp][f]}
// ---------------------------------------------------------------------------
__global__ void k_wpack(const float* __restrict__ W1, const float* __restrict__ W2) {
    int t = blockIdx.x * blockDim.x + threadIdx.x;
    if (t >= 5 * NF * NF) return;
    int f = t & 63, fp = (t >> 6) & 63, q = t >> 12;
    int s0 = 2 * q, s1 = 2 * q + 1;
    float a = (s0 < 5) ? W1[(s0 * NF + fp) * NF + f] : W2[((s0 - 5) * NF + fp) * NF + f];
    float b = (s1 < 5) ? W1[(s1 * NF + fp) * NF + f] : W2[((s1 - 5) * NF + fp) * NF + f];
    g_Wpair[t] = make_float2(a, b);
}

// ---------------------------------------------------------------------------
// Radial GEMV over r-sorted pairs with Gaussian-window sparsity.
// 256 threads = 4 subgroups x 64 (f); each subgroup: 8 pairs, shared window.
// ---------------------------------------------------------------------------
__global__ __launch_bounds__(256) void k_gemv(const float* __restrict__ SE, int nPairs) {
    const int sub = threadIdx.x >> 6;
    const int f = threadIdx.x & 63;
    const int base = (blockIdx.x * 4 + sub) * NP;

    __shared__ float2 rE_sh[4][NP];
    __shared__ int    jz_sh[4][NP];
    __shared__ int    pid_sh[4][NP];
    __shared__ float2 rad2_sh[4][NP][NF];

    const int cnt = min(NP, nPairs - base);

    if (f < NP && f < cnt) {
        int p = g_pairIdxR[base + f];
        pid_sh[sub][f] = p;
        rE_sh[sub][f] = g_rEnv[p];
        jz_sh[sub][f] = g_jz[p];
    }
    __syncthreads();

    // shared window over the subgroup's 8 pairs
    const float INV_DELTA = 63.0f / 5.0f;
    const float DELTA = 5.0f / 63.0f;
    const float GC = -0.5f * INV_DELTA * INV_DELTA;
    int f0 = 64, f1 = 0;
    for (int p = 0; p < cnt; p++) {
        float r = rE_sh[sub][p].x;
        int c = (int)(r * INV_DELTA);
        f0 = min(f0, c - 8);
        f1 = max(f1, c + 10);
    }
    f0 = max(f0, 0); f1 = min(f1, 64);
    const int win = max(f1 - f0, 0);

    // fill rad (duplicated for packed broadcast)
#pragma unroll
    for (int i = 0; i < NP; i++) {
        int idx = i * 64 + f;
        int p = i, fr = f;
        if (fr < win) {
            float v = 0.0f;
            if (p < cnt) {
                float2 re = rE_sh[sub][p];
                float d = re.x - (float)(f0 + fr) * DELTA;
                v = __expf(GC * d * d) * re.y * SE[jz_sh[sub][p] * NF + (f0 + fr)];
            }
            rad2_sh[sub][p][fr] = make_float2(v, v);
        }
    }
    __syncthreads();

    if (cnt <= 0) return;

    float2 acc2[NP][NSLOT2];
#pragma unroll
    for (int p = 0; p < NP; p++)
#pragma unroll
        for (int q = 0; q < NSLOT2; q++) acc2[p][q] = make_float2(0.0f, 0.0f);

    for (int fr = 0; fr < win; fr++) {
        int fp = f0 + fr;
        float2 w[NSLOT2];
#pragma unroll
        for (int q = 0; q < NSLOT2; q++) w[q] = g_Wpair[(q * NF + fp) * NF + f];
#pragma unroll
        for (int p = 0; p < NP; p++) {
            float2 rv2 = rad2_sh[sub][p][fr];
#pragma unroll
            for (int q = 0; q < NSLOT2; q++) ffma2(acc2[p][q], rv2, w[q]);
        }
    }

#pragma unroll
    for (int p = 0; p < NP; p++) {
        if (p >= cnt) break;
        float2* dst = g_RAB + (size_t)pid_sh[sub][p] * 320 + f;
#pragma unroll
        for (int q = 0; q < NSLOT2; q++) dst[q * 64] = acc2[p][q];
    }
}

// ---------------------------------------------------------------------------
// Main fused kernel: one block (64 threads) per atom; thread = feature f.
// ---------------------------------------------------------------------------
__global__ __launch_bounds__(64, 8) void k_main(
    const int* __restrict__ Z, const float* __restrict__ disp,
    const float* __restrict__ SE, const float* __restrict__ Wt,
    const float* __restrict__ bt, const float* __restrict__ b1,
    const float* __restrict__ b2, float* __restrict__ out)
{
    const int a = blockIdx.x;
    const int f = threadIdx.x;

    __shared__ float se_sh[NF];
    __shared__ __align__(16) float Y_sh[NP][26];
    __shared__ __align__(16) float S_sh[NP][NS_PAD];
    __shared__ int pid_sh[NP];

    se_sh[f] = SE[Z[a] * NF + f];
    __syncthreads();
    float emb = bt[f];
#pragma unroll 8
    for (int g = 0; g < NF; g++) emb = fmaf(se_sh[g], Wt[g * NF + f], emb);

    const float b1f = b1[f] * 3.5449077018110318f;   // 1/Y00
    const float b2f = b2[f] * 3.5449077018110318f;

    float2 oa[13];
#pragma unroll
    for (int k = 0; k < 13; k++) oa[k] = make_float2(0.0f, 0.0f);

    const int p0 = g_off[a], p1 = g_off[a + 1];

    for (int base = p0; base < p1; base += NP) {
        const int np = min(NP, p1 - base);
        __syncthreads();

        // ---- Phase A: spherical harmonics (threads 0..np-1) ----
        if (f < np) {
            int p = g_pairIdx[base + f];
            pid_sh[f] = p;
            float dx = disp[3 * p], dy = disp[3 * p + 1], dz = disp[3 * p + 2];
            float inv = rsqrtf(dx * dx + dy * dy + dz * dz + 1e-12f);
            float x = dx * inv, y = dy * inv, z = dz * inv;
            float x2 = x * x, y2 = y * y, z2 = z * z;
            float* Yv = Y_sh[f];
            Yv[0]  = 0.28209479177387814f;
            Yv[1]  = 0.4886025119029199f * y;
            Yv[2]  = 0.4886025119029199f * z;
            Yv[3]  = 0.4886025119029199f * x;
            Yv[4]  = 1.0925484305920792f * x * y;
            Yv[5]  = 1.0925484305920792f * y * z;
            Yv[6]  = 0.31539156525252005f * (3.0f * z2 - 1.0f);
            Yv[7]  = 1.0925484305920792f * x * z;
            Yv[8]  = 0.5462742152960396f * (x2 - y2);
            Yv[9]  = 0.5900435899266435f * y * (3.0f * x2 - y2);
            Yv[10] = 2.890611442640554f * x * y * z;
            Yv[11] = 0.4570457994644658f * y * (5.0f * z2 - 1.0f);
            Yv[12] = 0.3731763325901154f * z * (5.0f * z2 - 3.0f);
            Yv[13] = 0.4570457994644658f * x * (5.0f * z2 - 1.0f);
            Yv[14] = 1.445305721320277f * z * (x2 - y2);
            Yv[15] = 0.5900435899266435f * x * (x2 - 3.0f * y2);
            Yv[16] = 2.5033429417967046f * x * y * (x2 - y2);
            Yv[17] = 1.7701307697799304f * y * z * (3.0f * x2 - y2);
            Yv[18] = 0.9461746957575601f * x * y * (7.0f * z2 - 1.0f);
            Yv[19] = 0.6690465435572892f * y * z * (7.0f * z2 - 3.0f);
            Yv[20] = 0.10578554691520431f * (35.0f * z2 * z2 - 30.0f * z2 + 3.0f);
            Yv[21] = 0.6690465435572892f * x * z * (7.0f * z2 - 3.0f);
            Yv[22] = 0.47308734787878004f * (x2 - y2) * (7.0f * z2 - 1.0f);
            Yv[23] = 1.7701307697799304f * x * z * (x2 - 3.0f * y2);
            Yv[24] = 0.6258357354491761f * (x2 * x2 - 6.0f * x2 * y2 + y2 * y2);
        }
        __syncthreads();

        // ---- Phase C: padded S rows; entries carry (coef, i, j) inline ----
#pragma unroll
        for (int t = 0; t < 7; t++) {
            int pos = t * NF + f;
            int row = g_tab.rowOrder[pos];
            if (row < 0) continue;
            int e0 = g_tab.rowStart[row], e1 = g_tab.rowStart[row + 1];
            float acc[NP];
#pragma unroll
            for (int p = 0; p < NP; p++) acc[p] = 0.0f;
            for (int e = e0; e < e1; e++) {
                unsigned long long v = g_tab.ent[e];
                int ij = (int)(unsigned int)v;
                int i = ij >> 5, j = ij & 31;
                float c = __int_as_float((int)(v >> 32));
#pragma unroll
                for (int p = 0; p < NP; p++)
                    acc[p] = fmaf(c, Y_sh[p][i] * Y_sh[p][j], acc[p]);
            }
#pragma unroll
            for (int p = 0; p < NP; p++) S_sh[p][row] = acc[p];
        }
        __syncthreads();

        // ---- Phase E: tensor product with RAB prefetch ----
        const float2* Rp = g_RAB + (size_t)pid_sh[0] * 320 + f;
        float2 nx[NSLOT2];
#pragma unroll
        for (int q = 0; q < NSLOT2; q++) nx[q] = Rp[q * 64];

        for (int p = 0; p < np; p++) {
            float2 cur[NSLOT2];
#pragma unroll
            for (int q = 0; q < NSLOT2; q++) cur[q] = nx[q];
            if (p + 1 < np) {
                const float2* Rn = g_RAB + (size_t)pid_sh[p + 1] * 320 + f;
#pragma unroll
                for (int q = 0; q < NSLOT2; q++) nx[q] = Rn[q * 64];
            }
            float ra[5], rb[5];
            ra[0] = cur[0].x + b1f; ra[1] = cur[0].y;
            ra[2] = cur[1].x;       ra[3] = cur[1].y;
            ra[4] = cur[2].x;
            rb[0] = cur[2].y + b2f; rb[1] = cur[3].x;
            rb[2] = cur[3].y;       rb[3] = cur[4].x;
            rb[4] = cur[4].y;
            const float* Sp = S_sh[p];
#define TP_TRI(L1, L2, L3, SO, IDX)                                             \
            {                                                                   \
                float prod = ra[L1] * rb[L2];                                   \
                float2 pr2 = make_float2(prod, prod);                           \
                _Pragma("unroll")                                               \
                for (int t = 0; t <= (L3); t++)                                 \
                    ffma2(oa[((L3) * (L3)) / 2 + t], pr2,                       \
                          *(const float2*)(Sp + (SO) + (IDX) + 2 * t));         \
            }
            TRI_LIST(TP_TRI)
#undef TP_TRI
        }
    }

    // ---- Epilogue: out[a][k][f] = emb * (acc[k] + (k==0)) ----
    float* o = out + (size_t)a * FDIM * NF + f;
    oa[0].x += 1.0f;
#pragma unroll
    for (int t = 0; t < 12; t++) {
        o[(2 * t) * NF]     = emb * oa[t].x;
        o[(2 * t + 1) * NF] = emb * oa[t].y;
    }
    o[24 * NF] = emb * oa[12].x;
}

// ---------------------------------------------------------------------------
// Launch
// ---------------------------------------------------------------------------
extern "C" void kernel_launch(void* const* d_in, const int* in_sizes, int n_in,
                              void* d_out, int out_size)
{
    const int*   Z    = (const int*)  d_in[0];
    const float* disp = (const float*)d_in[1];
    const int*   nbr  = (const int*)  d_in[2];
    const float* SE   = (const float*)d_in[3];
    const float* Wt   = (const float*)d_in[4];
    const float* bt   = (const float*)d_in[5];
    const float* W1   = (const float*)d_in[6];
    const float* b1   = (const float*)d_in[7];
    const float* W2   = (const float*)d_in[8];
    const float* b2   = (const float*)d_in[9];
    float* out = (float*)d_out;

    int nAtoms = in_sizes[0];
    int nPairs = in_sizes[1] / 3;
    if (nAtoms > NATOM_MAX || nPairs > NPAIR_MAX) return;

    cudaMemcpyToSymbolAsync(g_tab, &h_tab, h_tab_bytes, 0,
                            cudaMemcpyHostToDevice, 0);

    int tb = 256;
    k_wpack<<<(5 * NF * NF + tb - 1) / tb, tb>>>(W1, W2);
    k_zero<<<(nAtoms + tb - 1) / tb, tb>>>(nAtoms);
    k_prep<<<(nPairs + tb - 1) / tb, tb>>>(disp, nbr, Z, nPairs);
    k_scan<<<1, 1024>>>(nAtoms);
    k_scatter<<<(nPairs + tb - 1) / tb, tb>>>(nbr, nPairs);
    k_gemv<<<(nPairs + 31) / 32, 256>>>(SE, nPairs);
    k_main<<<nAtoms, 64>>>(Z, disp, SE, Wt, bt, b1, b2, out);
}